// round 8
// baseline (speedup 1.0000x reference)
#include <cuda_runtime.h>
#include <cuda_bf16.h>
#include <math.h>

#define NN 50000
#define EE 1600000
#define IND 256
#define OUTD 64
#define NH 4
typedef unsigned long long ull;

// ---------------- scratch (static device arrays; zero-initialized) ----------
__device__ float  g_x[NN * OUTD];          // 12.8 MB  x = h@W
__device__ float4 g_el[NN];
__device__ float4 g_er[NN];
__device__ int    g_deg[NN];               // invariant: zero at kernel_launch entry
__device__ int    g_off[NN + 1];
__device__ int    g_cur[NN];
__device__ int    g_dst_s[EE];             // CSR-sorted dst

// ---------------- helpers ----------------------------------------------------
#define L2E 1.4426950408889634f

__device__ __forceinline__ float lrelu_exp(float v)
{
    return exp2f(fmaxf(v, 0.2f * v) * L2E);
}
__device__ __forceinline__ float elu1(float v)
{
    return (v > 0.f) ? v : expm1f(v);
}
__device__ __forceinline__ ull dup2(float v)
{
    ull r; asm("mov.b64 %0, {%1, %1};" : "=l"(r) : "f"(v)); return r;
}
union U64 { ull u; float2 f; };

// ---------------- K1: x = h @ W  + fused el/er projections -------------------
__global__ void k_gemm(const float* __restrict__ h, const float* __restrict__ W,
                       const float* __restrict__ Wl, const float* __restrict__ Wr,
                       int N)
{
    __shared__ float  As2[32][132];     // k-major, m-contiguous, pad 132
    __shared__ float4 Bs[32 * 16];

    const int tid = threadIdx.x;
    const int m0  = blockIdx.x * 128;
    const int tx  = tid & 15;
    const int ty  = tid >> 4;

    ull acc2[4][4];
#pragma unroll
    for (int r = 0; r < 4; r++)
#pragma unroll
        for (int j = 0; j < 4; j++) acc2[r][j] = 0ull;

    for (int k0 = 0; k0 < IND; k0 += 32) {
#pragma unroll
        for (int l = 0; l < 4; l++) {
            int f   = tid + 256 * l;
            int row = f >> 3;
            int kq  = f & 7;
            int gm  = m0 + row;
            float4 v = make_float4(0.f, 0.f, 0.f, 0.f);
            if (gm < N) v = *(const float4*)(h + (size_t)gm * IND + k0 + kq * 4);
            As2[kq * 4 + 0][row] = v.x;
            As2[kq * 4 + 1][row] = v.y;
            As2[kq * 4 + 2][row] = v.z;
            As2[kq * 4 + 3][row] = v.w;
        }
#pragma unroll
        for (int l = 0; l < 2; l++) {
            int f  = tid + 256 * l;
            int kk = f >> 4;
            int nq = f & 15;
            Bs[kk * 16 + nq] = *(const float4*)(W + (size_t)(k0 + kk) * OUTD + nq * 4);
        }
        __syncthreads();

#pragma unroll
        for (int k = 0; k < 32; k++) {
            const ull* ap = (const ull*)&As2[k][ty * 8];
            ull a[4] = {ap[0], ap[1], ap[2], ap[3]};
            float4 bv = Bs[k * 16 + tx];
            ull b0 = dup2(bv.x), b1 = dup2(bv.y), b2 = dup2(bv.z), b3 = dup2(bv.w);
#pragma unroll
            for (int r = 0; r < 4; r++) {
                asm("fma.rn.f32x2 %0, %1, %2, %0;" : "+l"(acc2[r][0]) : "l"(a[r]), "l"(b0));
                asm("fma.rn.f32x2 %0, %1, %2, %0;" : "+l"(acc2[r][1]) : "l"(a[r]), "l"(b1));
                asm("fma.rn.f32x2 %0, %1, %2, %0;" : "+l"(acc2[r][2]) : "l"(a[r]), "l"(b2));
                asm("fma.rn.f32x2 %0, %1, %2, %0;" : "+l"(acc2[r][3]) : "l"(a[r]), "l"(b3));
            }
        }
        __syncthreads();
    }

#pragma unroll
    for (int r = 0; r < 4; r++) {
        int gm0 = m0 + ty * 8 + 2 * r;
        U64 t0, t1, t2, t3;
        t0.u = acc2[r][0]; t1.u = acc2[r][1]; t2.u = acc2[r][2]; t3.u = acc2[r][3];
        if (gm0 < N)
            *(float4*)(g_x + (size_t)gm0 * OUTD + tx * 4) =
                make_float4(t0.f.x, t1.f.x, t2.f.x, t3.f.x);
        if (gm0 + 1 < N)
            *(float4*)(g_x + (size_t)(gm0 + 1) * OUTD + tx * 4) =
                make_float4(t0.f.y, t1.f.y, t2.f.y, t3.f.y);
    }

    // ---- fused el/er epilogue: STGs above become block-visible after sync ----
    __syncthreads();

    const int wrp  = tid >> 5;
    const int lane = tid & 31;

    float wl0[NH], wl1[NH], wr0[NH], wr1[NH];
#pragma unroll
    for (int p = 0; p < NH; p++) {
        wl0[p] = __ldg(Wl + p * OUTD + lane);
        wl1[p] = __ldg(Wl + p * OUTD + lane + 32);
        wr0[p] = __ldg(Wr + p * OUTD + lane);
        wr1[p] = __ldg(Wr + p * OUTD + lane + 32);
    }

#pragma unroll 2
    for (int rr = 0; rr < 16; rr++) {
        int row = m0 + wrp * 16 + rr;        // uniform per warp
        if (row >= N) break;
        float x0 = g_x[(size_t)row * OUTD + lane];
        float x1 = g_x[(size_t)row * OUTD + lane + 32];
        float s[8];
#pragma unroll
        for (int p = 0; p < NH; p++) {
            s[p]     = x0 * wl0[p] + x1 * wl1[p];
            s[4 + p] = x0 * wr0[p] + x1 * wr1[p];
        }
#pragma unroll
        for (int o = 16; o > 0; o >>= 1) {
#pragma unroll
            for (int j = 0; j < 8; j++) s[j] += __shfl_xor_sync(0xffffffffu, s[j], o);
        }
        if (lane == 0) {
            g_el[row] = make_float4(s[0], s[1], s[2], s[3]);
            g_er[row] = make_float4(s[4], s[5], s[6], s[7]);
        }
    }
}

// ---------------- K2: degree histogram ---------------------------------------
__global__ void k_deg(const int* __restrict__ ei, int E)
{
    int stride = gridDim.x * blockDim.x;
    const int4* e4 = (const int4*)ei;
    int E4 = E >> 2;
    for (int i = blockIdx.x * blockDim.x + threadIdx.x; i < E4; i += stride) {
        int4 v = e4[i];
        atomicAdd(&g_deg[v.x], 1);
        atomicAdd(&g_deg[v.y], 1);
        atomicAdd(&g_deg[v.z], 1);
        atomicAdd(&g_deg[v.w], 1);
    }
    for (int e = (E & ~3) + blockIdx.x * blockDim.x + threadIdx.x; e < E; e += stride)
        atomicAdd(&g_deg[ei[e]], 1);
}

// ---------------- K3: exclusive scan + deg re-zero ---------------------------
__global__ void k_scan(int N)
{
    __shared__ int sm[1024];
    const int t  = threadIdx.x;
    const int CH = (N + 1023) / 1024;
    int beg = t * CH;
    int end = beg + CH; if (end > N) end = N;

    int s = 0;
    for (int i = beg; i < end; i++) s += g_deg[i];
    sm[t] = s;
    __syncthreads();
#pragma unroll
    for (int o = 1; o < 1024; o <<= 1) {
        int v = (t >= o) ? sm[t - o] : 0;
        __syncthreads();
        sm[t] += v;
        __syncthreads();
    }
    int run = sm[t] - s;
    for (int i = beg; i < end; i++) {
        int dv = g_deg[i];
        g_off[i] = run;
        g_cur[i] = run;
        g_deg[i] = 0;
        run += dv;
    }
    if (t == 1023) g_off[N] = sm[1023];
}

// ---------------- K4: CSR scatter (dst only), 4 edges/thread -----------------
__global__ void k_scatter(const int* __restrict__ ei, int E)
{
    int i = blockIdx.x * blockDim.x + threadIdx.x;
    int e = i * 4;
    if (((E & 3) == 0) && (e + 4 <= E)) {
        int4 s4 = *(const int4*)(ei + e);
        int4 d4 = *(const int4*)(ei + E + e);
        g_dst_s[atomicAdd(&g_cur[s4.x], 1)] = d4.x;
        g_dst_s[atomicAdd(&g_cur[s4.y], 1)] = d4.y;
        g_dst_s[atomicAdd(&g_cur[s4.z], 1)] = d4.z;
        g_dst_s[atomicAdd(&g_cur[s4.w], 1)] = d4.w;
    } else {
        for (int q = e; q < E && q < e + 4; q++) {
            int s = ei[q];
            int d = ei[E + q];
            g_dst_s[atomicAdd(&g_cur[s], 1)] = d;
        }
    }
}

// ---------------- K5: per-node aggregation (register prefetch chain) ---------
__global__ void __launch_bounds__(128) k_agg(const float* __restrict__ b,
                                             float* __restrict__ out, int N)
{
    __shared__ int    s_off[4][32];
    __shared__ float4 s_e[4][32][2];     // (ex,ex,ey,ey) , (ez,ez,ew,ew)

    const int w    = threadIdx.x >> 5;
    const int lane = threadIdx.x & 31;
    const int node = blockIdx.x * 4 + w;
    if (node >= N) return;

    const int s0 = g_off[node];
    const int s1 = g_off[node + 1];

    float2 bb = *(const float2*)(b + lane * 2);
    float* o = out + (size_t)node * (NH * OUTD) + lane * 2;

    if (s0 >= s1) {                      // degree 0: out = elu(b)
        float2 r; r.x = elu1(bb.x); r.y = elu1(bb.y);
        *(float2*)(o + 0 * OUTD) = r;
        *(float2*)(o + 1 * OUTD) = r;
        *(float2*)(o + 2 * OUTD) = r;
        *(float2*)(o + 3 * OUTD) = r;
        return;
    }

    const float4 el = g_el[node];
    const int last = s1 - 1;

    ull a0 = 0ull, a1 = 0ull, a2 = 0ull, a3 = 0ull;
    float e0 = 0.f, e1 = 0.f, e2 = 0.f, e3 = 0.f;

    const float* xl = g_x + lane * 2;

    auto consume32 = [&]() {
        int oo0[4], oo1[4]; ull xx0[4], xx1[4];
#pragma unroll
        for (int q = 0; q < 4; q++) oo0[q] = s_off[w][q];
#pragma unroll
        for (int q = 0; q < 4; q++) xx0[q] = *(const ull*)(xl + oo0[q]);
#pragma unroll
        for (int g = 0; g < 8; g++) {
            if (g < 7) {
#pragma unroll
                for (int q = 0; q < 4; q++) oo1[q] = s_off[w][(g + 1) * 4 + q];
#pragma unroll
                for (int q = 0; q < 4; q++) xx1[q] = *(const ull*)(xl + oo1[q]);
            }
            ulonglong2 pa[4], pb[4];
#pragma unroll
            for (int q = 0; q < 4; q++) {
                pa[q] = *(const ulonglong2*)&s_e[w][g * 4 + q][0];
                pb[q] = *(const ulonglong2*)&s_e[w][g * 4 + q][1];
            }
#pragma unroll
            for (int q = 0; q < 4; q++) {
                asm("fma.rn.f32x2 %0, %1, %2, %0;" : "+l"(a0) : "l"(pa[q].x), "l"(xx0[q]));
                asm("fma.rn.f32x2 %0, %1, %2, %0;" : "+l"(a1) : "l"(pa[q].y), "l"(xx0[q]));
                asm("fma.rn.f32x2 %0, %1, %2, %0;" : "+l"(a2) : "l"(pb[q].x), "l"(xx0[q]));
                asm("fma.rn.f32x2 %0, %1, %2, %0;" : "+l"(a3) : "l"(pb[q].y), "l"(xx0[q]));
            }
#pragma unroll
            for (int q = 0; q < 4; q++) { xx0[q] = xx1[q]; oo0[q] = oo1[q]; }
        }
    };

    auto consumeTail = [&](int n) {
        for (int j = 0; j < n; j++) {
            int off = s_off[w][j];
            ulonglong2 p0 = *(const ulonglong2*)&s_e[w][j][0];
            ulonglong2 p1 = *(const ulonglong2*)&s_e[w][j][1];
            ull xv = *(const ull*)(xl + off);
            asm("fma.rn.f32x2 %0, %1, %2, %0;" : "+l"(a0) : "l"(p0.x), "l"(xv));
            asm("fma.rn.f32x2 %0, %1, %2, %0;" : "+l"(a1) : "l"(p0.y), "l"(xv));
            asm("fma.rn.f32x2 %0, %1, %2, %0;" : "+l"(a2) : "l"(p1.x), "l"(xv));
            asm("fma.rn.f32x2 %0, %1, %2, %0;" : "+l"(a3) : "l"(p1.y), "l"(xv));
        }
    };

    // register prefetch chain: dst two chunks ahead, er one chunk ahead
    int c = s0;
    int n = (s1 - c) < 32 ? (s1 - c) : 32;

    int iA = c + lane;       if (iA > last) iA = last;
    int dA = g_dst_s[iA];
    float4 erA = g_er[dA];                       // exposed once
    int iB = c + 32 + lane;  if (iB > last) iB = last;
    int dB = g_dst_s[iB];

    while (true) {
        int iC = c + 64 + lane; if (iC > last) iC = last;
        int dC = g_dst_s[iC];                    // prefetch dst (2 ahead)
        float4 erB = g_er[dB];                   // prefetch er (1 ahead; dB is old)

        // stage current chunk from (dA, erA): pure ALU
        if (lane < n) {
            float ex = lrelu_exp(el.x + erA.x);
            float ey = lrelu_exp(el.y + erA.y);
            float ez = lrelu_exp(el.z + erA.z);
            float ew = lrelu_exp(el.w + erA.w);
            e0 += ex; e1 += ey; e2 += ez; e3 += ew;
            s_off[w][lane]  = dA * OUTD;
            s_e[w][lane][0] = make_float4(ex, ex, ey, ey);
            s_e[w][lane][1] = make_float4(ez, ez, ew, ew);
        }
        __syncwarp();

        if (c + 32 >= s1) {                      // this is the last chunk
            if (n == 32) consume32(); else consumeTail(n);
            break;
        }
        consume32();                             // full chunk (next one exists)
        __syncwarp();

        c += 32;
        n = (s1 - c) < 32 ? (s1 - c) : 32;
        dA = dB; erA = erB; dB = dC;
    }

#pragma unroll
    for (int oo = 16; oo > 0; oo >>= 1) {
        e0 += __shfl_xor_sync(0xffffffffu, e0, oo);
        e1 += __shfl_xor_sync(0xffffffffu, e1, oo);
        e2 += __shfl_xor_sync(0xffffffffu, e2, oo);
        e3 += __shfl_xor_sync(0xffffffffu, e3, oo);
    }

    float i0 = 1.f / fmaxf(e0, 1e-12f);
    float i1 = 1.f / fmaxf(e1, 1e-12f);
    float i2 = 1.f / fmaxf(e2, 1e-12f);
    float i3 = 1.f / fmaxf(e3, 1e-12f);

    U64 A0, A1, A2, A3;
    A0.u = a0; A1.u = a1; A2.u = a2; A3.u = a3;

    float2 r;
    r.x = elu1(A0.f.x * i0 + bb.x); r.y = elu1(A0.f.y * i0 + bb.y);
    *(float2*)(o + 0 * OUTD) = r;
    r.x = elu1(A1.f.x * i1 + bb.x); r.y = elu1(A1.f.y * i1 + bb.y);
    *(float2*)(o + 1 * OUTD) = r;
    r.x = elu1(A2.f.x * i2 + bb.x); r.y = elu1(A2.f.y * i2 + bb.y);
    *(float2*)(o + 2 * OUTD) = r;
    r.x = elu1(A3.f.x * i3 + bb.x); r.y = elu1(A3.f.y * i3 + bb.y);
    *(float2*)(o + 3 * OUTD) = r;
}

// ---------------- launch: fork-join two-stream graph --------------------------
extern "C" void kernel_launch(void* const* d_in, const int* in_sizes, int n_in,
                              void* d_out, int out_size)
{
    const float* h  = (const float*)d_in[0];   // [N, 256]
    const float* W  = (const float*)d_in[1];   // [256, 64]
    const float* Wl = (const float*)d_in[2];   // [4, 64]
    const float* Wr = (const float*)d_in[3];   // [4, 64]
    const float* b  = (const float*)d_in[4];   // [64]
    const int*   ei = (const int*)d_in[5];     // [2, E]
    float* out = (float*)d_out;

    int N = in_sizes[0] / IND;
    int E = in_sizes[5] / 2;

    static cudaStream_t s1 = nullptr;
    static cudaEvent_t  evFork = nullptr, evJoin = nullptr;
    if (s1 == nullptr) {
        cudaStreamCreateWithFlags(&s1, cudaStreamNonBlocking);
        cudaEventCreateWithFlags(&evFork, cudaEventDisableTiming);
        cudaEventCreateWithFlags(&evJoin, cudaEventDisableTiming);
    }

    // fork: s1 handles the CSR-build chain (independent of the GEMM)
    cudaEventRecord(evFork, 0);
    cudaStreamWaitEvent(s1, evFork, 0);

    k_deg<<<512, 256, 0, s1>>>(ei, E);
    k_scan<<<1, 1024, 0, s1>>>(N);
    int SB = ((E + 3) / 4 + 255) / 256;
    k_scatter<<<SB, 256, 0, s1>>>(ei, E);
    cudaEventRecord(evJoin, s1);

    // main stream: fused gemm + el/er
    k_gemm<<<(N + 127) / 128, 256>>>(h, W, Wl, Wr, N);

    // join: agg needs CSR (s1) + x/el/er (main)
    cudaStreamWaitEvent(0, evJoin, 0);
    k_agg<<<(N + 3) / 4, 128>>>(b, out, N);
}